// round 9
// baseline (speedup 1.0000x reference)
#include <cuda_runtime.h>
#include <cstdint>

#define Bb 16
#define Nn 16
#define Hh 512
#define Ww 512
#define HW  (Hh * Ww)
#define HW4 (HW / 4)                  // 65536 float4 per slice
#define THREADS 256
#define NG 4
#define NGROUPS (Nn / NG)             // 4
#define SPLIT 8
#define CHUNK_F4 (HW4 / SPLIT)        // 8192 float4 per tensor per block
#define STAGE_F4 THREADS              // 256 float4 per tensor per stage
#define STAGES (CHUNK_F4 / STAGE_F4)  // 32
#define GRID_S (Bb * NGROUPS * SPLIT) // 512 stream blocks
#define BOX_BLOCKS 64                 // 4 boxes each
#define GRID_T (GRID_S + BOX_BLOCKS)  // 576

__device__ float    g_ov[Bb * Nn];
__device__ float    g_it[Bb * Nn];
__device__ float    g_ts[Bb];
__device__ unsigned g_done;

__device__ __forceinline__ void cpa16(uint32_t dst, const void* src) {
    asm volatile("cp.async.cg.shared.global [%0], [%1], 16;\n" :: "r"(dst), "l"(src));
}

__global__ __launch_bounds__(THREADS)
void fused5_kernel(const float* __restrict__ masks,
                   const float* __restrict__ target,
                   const int*   __restrict__ boxes,
                   float*       __restrict__ out)
{
    __shared__ float4 buf[2][NG + 1][STAGE_F4];   // 40 KB
    __shared__ float  s_red[THREADS / 32][5];

    const int tid = threadIdx.x;
    const int wid = tid >> 5;
    const int lid = tid & 31;
    const unsigned FULL = 0xFFFFFFFFu;

    if (blockIdx.x < GRID_S) {
        // ============ stream blocks: ov[4] + ts via cp.async pipeline ============
        const int blk = blockIdx.x;
        const int b   = blk >> 5;          // / (NGROUPS*SPLIT)
        const int rest = blk & 31;
        const int ng  = rest >> 3;         // 0..3
        const int sp  = rest & 7;          // 0..7

        const size_t coff = (size_t)sp * CHUNK_F4 + tid;
        const float4* __restrict__ tp = (const float4*)target + (size_t)b * HW4 + coff;
        const float4* __restrict__ mp[NG];
        #pragma unroll
        for (int j = 0; j < NG; j++)
            mp[j] = (const float4*)masks + ((size_t)(b * Nn + ng * NG + j)) * HW4 + coff;

        // smem byte addresses for this thread's slot in each buffer
        uint32_t sdst[2][NG + 1];
        #pragma unroll
        for (int p = 0; p < 2; p++)
            #pragma unroll
            for (int q = 0; q < NG + 1; q++)
                sdst[p][q] = (uint32_t)__cvta_generic_to_shared(&buf[p][q][tid]);

        // issue stage 0
        {
            cpa16(sdst[0][NG], tp);
            #pragma unroll
            for (int j = 0; j < NG; j++) cpa16(sdst[0][j], mp[j]);
            asm volatile("cp.async.commit_group;\n");
        }

        float ov0 = 0.f, ov1 = 0.f, ov2 = 0.f, ov3 = 0.f, ts = 0.f;

        for (int s = 0; s < STAGES; s++) {
            const int p = s & 1;
            if (s + 1 < STAGES) {
                const int off = (s + 1) * STAGE_F4;
                cpa16(sdst[p ^ 1][NG], tp + off);
                #pragma unroll
                for (int j = 0; j < NG; j++) cpa16(sdst[p ^ 1][j], mp[j] + off);
                asm volatile("cp.async.commit_group;\n");
                asm volatile("cp.async.wait_group 1;\n");
            } else {
                asm volatile("cp.async.wait_group 0;\n");
            }
            __syncthreads();

            const float4 tv = buf[p][NG][tid];
            const float4 v0 = buf[p][0][tid];
            const float4 v1 = buf[p][1][tid];
            const float4 v2 = buf[p][2][tid];
            const float4 v3 = buf[p][3][tid];

            ts += (tv.x + tv.y) + (tv.z + tv.w);
            ov0 = fmaf(v0.x, tv.x, ov0); ov0 = fmaf(v0.y, tv.y, ov0);
            ov0 = fmaf(v0.z, tv.z, ov0); ov0 = fmaf(v0.w, tv.w, ov0);
            ov1 = fmaf(v1.x, tv.x, ov1); ov1 = fmaf(v1.y, tv.y, ov1);
            ov1 = fmaf(v1.z, tv.z, ov1); ov1 = fmaf(v1.w, tv.w, ov1);
            ov2 = fmaf(v2.x, tv.x, ov2); ov2 = fmaf(v2.y, tv.y, ov2);
            ov2 = fmaf(v2.z, tv.z, ov2); ov2 = fmaf(v2.w, tv.w, ov2);
            ov3 = fmaf(v3.x, tv.x, ov3); ov3 = fmaf(v3.y, tv.y, ov3);
            ov3 = fmaf(v3.z, tv.z, ov3); ov3 = fmaf(v3.w, tv.w, ov3);

            __syncthreads();     // protect buffer reuse at stage s+2
        }

        float v[5] = {ov0, ov1, ov2, ov3, ts};
        #pragma unroll
        for (int q = 0; q < 5; q++) {
            #pragma unroll
            for (int off = 16; off > 0; off >>= 1)
                v[q] += __shfl_xor_sync(FULL, v[q], off);
        }
        if (lid == 0) {
            #pragma unroll
            for (int q = 0; q < 5; q++) s_red[wid][q] = v[q];
        }
        __syncthreads();

        if (tid < 5) {
            float sum = 0.f;
            #pragma unroll
            for (int w = 0; w < THREADS / 32; w++) sum += s_red[w][tid];
            if (tid < 4) {
                atomicAdd(&g_ov[b * Nn + ng * NG + tid], sum);
            } else if (ng == 0) {       // ts once per (b, chunk)
                atomicAdd(&g_ts[b], sum);
            }
        }
    } else {
        // ============ box blocks: intersection (4 boxes each) ============
        const int base_bn = (blockIdx.x - GRID_S) * 4;
        for (int j = 0; j < 4; j++) {
            const int bn = base_bn + j;
            const int b  = bn >> 4;
            const int4 bx = __ldg((const int4*)boxes + bn);
            const float* __restrict__ t = target + (size_t)b * HW;

            float it = 0.f;
            const int r_off = tid >> 6;      // 0..3
            const int c_off = tid & 63;      // 0..63
            for (int h = bx.y + r_off; h < bx.w; h += 4) {
                const float* row = t + h * Ww;
                for (int w = bx.x + c_off; w < bx.z; w += 64) {
                    it += __ldg(row + w);
                }
            }
            #pragma unroll
            for (int off = 16; off > 0; off >>= 1)
                it += __shfl_xor_sync(FULL, it, off);
            if (lid == 0) s_red[wid][0] = it;
            __syncthreads();
            if (tid == 0) {
                float sum = 0.f;
                #pragma unroll
                for (int w = 0; w < THREADS / 32; w++) sum += s_red[w][0];
                g_it[bn] = sum;          // single writer per bn
            }
            __syncthreads();
        }
    }

    __threadfence();
    __syncthreads();

    __shared__ unsigned s_last;
    if (tid == 0) s_last = atomicAdd(&g_done, 1u);
    __syncthreads();

    // ---- last block finalizes + resets (graph-replay safe) ----
    if (s_last == GRID_T - 1) {
        const int bn = tid;   // 0..255
        const float ovv = *(volatile float*)&g_ov[bn];
        const float itv = *(volatile float*)&g_it[bn];
        const float tsv = *(volatile float*)&g_ts[bn >> 4];
        const int4 bx = reinterpret_cast<const int4*>(boxes)[bn];
        const float area = (float)(bx.z - bx.x) * (float)(bx.w - bx.y);
        const float uni = area + tsv - itv;
        out[bn * 2 + 0] = ovv;
        out[bn * 2 + 1] = itv / (uni + 1e-8f);
        g_ov[bn] = 0.f;
        g_it[bn] = 0.f;
        if (bn < Bb) g_ts[bn] = 0.f;
        if (bn == 0) g_done = 0u;
    }
}

extern "C" void kernel_launch(void* const* d_in, const int* in_sizes, int n_in,
                              void* d_out, int out_size)
{
    const float* masks  = (const float*)d_in[0];   // (B,N,H,W) f32
    const float* target = (const float*)d_in[1];   // (B,H,W)   f32
    const int*   boxes  = (const int*)d_in[2];     // (B,N,4)   i32
    float* out = (float*)d_out;                    // (B,N,2)   f32

    fused5_kernel<<<GRID_T, THREADS>>>(masks, target, boxes, out);
}